// round 2
// baseline (speedup 1.0000x reference)
#include <cuda_runtime.h>
#include <cstdint>

#define TILE 128
#define D 64
#define NTHREADS 256

__device__ __forceinline__ unsigned long long splat2(float v) {
    unsigned long long r;
    unsigned u = __float_as_uint(v);
    asm("mov.b64 %0, {%1, %1};" : "=l"(r) : "r"(u));
    return r;
}

__device__ __forceinline__ void fma2(unsigned long long& d,
                                     unsigned long long a,
                                     unsigned long long b) {
    asm("fma.rn.f32x2 %0, %1, %2, %0;" : "+l"(d) : "l"(a), "l"(b));
}

__device__ __forceinline__ float2 unpack2(unsigned long long v) {
    unsigned lo, hi;
    asm("mov.b64 {%0, %1}, %2;" : "=r"(lo), "=r"(hi) : "l"(v));
    float2 f;
    f.x = __uint_as_float(lo);
    f.y = __uint_as_float(hi);
    return f;
}

extern __shared__ float smem_dyn[];

__global__ __launch_bounds__(NTHREADS, 2)
void PairwiseDistance_kernel(const float* __restrict__ x,
                             const float* __restrict__ y,
                             float* __restrict__ out, int n) {
    // smem layout: xs[D][TILE], ys[D][TILE], xn[TILE], yn[TILE]  (k-major tiles)
    float* xs = smem_dyn;                 // D*TILE floats
    float* ys = smem_dyn + D * TILE;      // D*TILE floats
    float* xn = smem_dyn + 2 * D * TILE;  // TILE floats
    float* yn = xn + TILE;                // TILE floats

    const int b  = blockIdx.z;
    const int i0 = blockIdx.y * TILE;
    const int j0 = blockIdx.x * TILE;
    const float* xb = x + (size_t)b * n * D;
    const float* yb = y + (size_t)b * n * D;
    float* ob = out + (size_t)b * n * n;

    const int tid = threadIdx.x;

    // ---- Load tiles (transpose to k-major in smem) ----
    // 128 rows x 64 cols per tile; 2048 float4 per tile; 8 per thread.
    #pragma unroll
    for (int it = 0; it < 8; it++) {
        int idx = tid + it * NTHREADS;     // 0..2047
        int row = idx & (TILE - 1);        // 0..127
        int c4  = idx >> 7;                // 0..15
        float4 xv = *(const float4*)(xb + (size_t)(i0 + row) * D + c4 * 4);
        xs[(c4 * 4 + 0) * TILE + row] = xv.x;
        xs[(c4 * 4 + 1) * TILE + row] = xv.y;
        xs[(c4 * 4 + 2) * TILE + row] = xv.z;
        xs[(c4 * 4 + 3) * TILE + row] = xv.w;
        float4 yv = *(const float4*)(yb + (size_t)(j0 + row) * D + c4 * 4);
        ys[(c4 * 4 + 0) * TILE + row] = yv.x;
        ys[(c4 * 4 + 1) * TILE + row] = yv.y;
        ys[(c4 * 4 + 2) * TILE + row] = yv.z;
        ys[(c4 * 4 + 3) * TILE + row] = yv.w;
    }
    __syncthreads();

    // ---- Row norms (threads 0-127 -> x, 128-255 -> y) ----
    {
        int t = tid & 127;
        const float* s = (tid < 128) ? xs : ys;
        float* dst     = (tid < 128) ? xn : yn;
        float acc = 0.0f;
        #pragma unroll
        for (int k = 0; k < D; k++) {
            float v = s[k * TILE + t];
            acc = fmaf(v, v, acc);
        }
        dst[t] = acc;
    }
    __syncthreads();

    // ---- Main 8x8 register-tile dot products via f32x2 packed FMA ----
    const int ty = tid >> 4;      // 0..15 -> row chunk
    const int tx = tid & 15;      // 0..15 -> col chunks (split)
    const int ib = ty * 8;        // 8 contiguous i rows
    const int jb = tx * 4;        // cols jb..jb+3 and 64+jb..64+jb+3

    unsigned long long acc[8][4];
    #pragma unroll
    for (int i = 0; i < 8; i++)
        #pragma unroll
        for (int j = 0; j < 4; j++)
            acc[i][j] = 0ULL;

    #pragma unroll 8
    for (int k = 0; k < D; k++) {
        const float* xr = xs + k * TILE + ib;
        float4 xa  = *(const float4*)(xr);
        float4 xb4 = *(const float4*)(xr + 4);
        unsigned long long xp[8];
        xp[0] = splat2(xa.x);  xp[1] = splat2(xa.y);
        xp[2] = splat2(xa.z);  xp[3] = splat2(xa.w);
        xp[4] = splat2(xb4.x); xp[5] = splat2(xb4.y);
        xp[6] = splat2(xb4.z); xp[7] = splat2(xb4.w);

        const float* yr = ys + k * TILE + jb;
        ulonglong2 ya = *(const ulonglong2*)(yr);        // cols jb..jb+3
        ulonglong2 yc = *(const ulonglong2*)(yr + 64);   // cols 64+jb..64+jb+3
        unsigned long long yp[4];
        yp[0] = ya.x; yp[1] = ya.y; yp[2] = yc.x; yp[3] = yc.y;

        #pragma unroll
        for (int i = 0; i < 8; i++) {
            #pragma unroll
            for (int j = 0; j < 4; j++)
                fma2(acc[i][j], xp[i], yp[j]);
        }
    }

    // ---- Epilogue: out = xn + yn - 2*dot ----
    float4 yn0 = *(const float4*)(yn + jb);
    float4 yn1 = *(const float4*)(yn + 64 + jb);

    #pragma unroll
    for (int i = 0; i < 8; i++) {
        float xni = xn[ib + i];
        float2 a0 = unpack2(acc[i][0]);
        float2 a1 = unpack2(acc[i][1]);
        float2 a2 = unpack2(acc[i][2]);
        float2 a3 = unpack2(acc[i][3]);

        float4 o0;
        o0.x = xni + yn0.x - 2.0f * a0.x;
        o0.y = xni + yn0.y - 2.0f * a0.y;
        o0.z = xni + yn0.z - 2.0f * a1.x;
        o0.w = xni + yn0.w - 2.0f * a1.y;
        float4 o1;
        o1.x = xni + yn1.x - 2.0f * a2.x;
        o1.y = xni + yn1.y - 2.0f * a2.y;
        o1.z = xni + yn1.z - 2.0f * a3.x;
        o1.w = xni + yn1.w - 2.0f * a3.y;

        size_t rowoff = (size_t)(i0 + ib + i) * n + j0;
        *(float4*)(ob + rowoff + jb)      = o0;
        *(float4*)(ob + rowoff + 64 + jb) = o1;
    }
}

extern "C" void kernel_launch(void* const* d_in, const int* in_sizes, int n_in,
                              void* d_out, int out_size) {
    const float* x = (const float*)d_in[0];
    const float* y = (const float*)d_in[1];
    float* out = (float*)d_out;

    const int B = 2;
    int n = in_sizes[0] / (B * D);         // 2048 for this problem
    if (n <= 0) n = 2048;

    size_t smem_bytes = (size_t)(2 * D * TILE + 2 * TILE) * sizeof(float);  // 66560
    cudaFuncSetAttribute(PairwiseDistance_kernel,
                         cudaFuncAttributeMaxDynamicSharedMemorySize,
                         (int)smem_bytes);

    dim3 grid(n / TILE, n / TILE, B);
    PairwiseDistance_kernel<<<grid, NTHREADS, smem_bytes>>>(x, y, out, n);
}

// round 4
// speedup vs baseline: 1.2119x; 1.2119x over previous
#include <cuda_runtime.h>
#include <cuda_bf16.h>
#include <cstdint>

#define TILE 128
#define Dk 64
#define NTHREADS 256

// smem float offsets
#define SM_XHI 0
#define SM_XLO 16384
#define SM_YHI 32768
#define SM_YLO 49152
#define SM_XN  65536
#define SM_YN  66048
#define SM_TOTAL 66560   // bytes

__device__ __forceinline__ uint32_t smem_u32(const void* p) {
    uint32_t a;
    asm("{ .reg .u64 t; cvta.to.shared.u64 t, %1; cvt.u32.u64 %0, t; }" : "=r"(a) : "l"(p));
    return a;
}

__device__ __forceinline__ void ldsm_x4(uint32_t addr, uint32_t& r0, uint32_t& r1,
                                        uint32_t& r2, uint32_t& r3) {
    asm volatile("ldmatrix.sync.aligned.m8n8.x4.shared.b16 {%0,%1,%2,%3}, [%4];"
                 : "=r"(r0), "=r"(r1), "=r"(r2), "=r"(r3) : "r"(addr));
}

__device__ __forceinline__ void mma16816(float& c0, float& c1, float& c2, float& c3,
                                         uint32_t a0, uint32_t a1, uint32_t a2, uint32_t a3,
                                         uint32_t b0, uint32_t b1) {
    asm volatile(
        "mma.sync.aligned.m16n8k16.row.col.f32.bf16.bf16.f32 "
        "{%0,%1,%2,%3}, {%4,%5,%6,%7}, {%8,%9}, {%0,%1,%2,%3};"
        : "+f"(c0), "+f"(c1), "+f"(c2), "+f"(c3)
        : "r"(a0), "r"(a1), "r"(a2), "r"(a3), "r"(b0), "r"(b1));
}

extern __shared__ char smem[];

__global__ __launch_bounds__(NTHREADS, 2)
void PairwiseDistance_mma_kernel(const float* __restrict__ x,
                                 const float* __restrict__ y,
                                 float* __restrict__ out, int n) {
    const uint32_t sbase = smem_u32(smem);
    const int tid  = threadIdx.x;
    const int wid  = tid >> 5;
    const int lane = tid & 31;

    const int b  = blockIdx.z;
    const int i0 = blockIdx.y * TILE;
    const int j0 = blockIdx.x * TILE;
    const float* xb = x + (size_t)b * n * Dk;
    const float* yb = y + (size_t)b * n * Dk;
    float* ob = out + (size_t)b * n * n;

    float* xn = (float*)(smem + SM_XN);
    float* yn = (float*)(smem + SM_YN);

    // ---- Prologue: per-thread row -> bf16 hi/lo split (SW128 layout) + norm ----
    {
        const bool isx = (tid < 128);
        const int  rr  = tid & 127;
        const float scale = isx ? -2.0f : 1.0f;     // fold -2 into x side
        const float* src = isx ? (xb + (size_t)(i0 + rr) * Dk)
                               : (yb + (size_t)(j0 + rr) * Dk);
        char* hi_t = smem + (isx ? SM_XHI : SM_YHI);
        char* lo_t = smem + (isx ? SM_XLO : SM_YLO);

        float norm = 0.0f;
        #pragma unroll 4
        for (int i4 = 0; i4 < 16; i4++) {
            float4 v = *(const float4*)(src + i4 * 4);
            float e0 = v.x, e1 = v.y, e2 = v.z, e3 = v.w;
            norm = fmaf(e0, e0, norm); norm = fmaf(e1, e1, norm);
            norm = fmaf(e2, e2, norm); norm = fmaf(e3, e3, norm);
            float f0 = scale * e0, f1 = scale * e1, f2 = scale * e2, f3 = scale * e3;
            __nv_bfloat16 h0 = __float2bfloat16_rn(f0);
            __nv_bfloat16 h1 = __float2bfloat16_rn(f1);
            __nv_bfloat16 h2 = __float2bfloat16_rn(f2);
            __nv_bfloat16 h3 = __float2bfloat16_rn(f3);
            __nv_bfloat16 l0 = __float2bfloat16_rn(f0 - __bfloat162float(h0));
            __nv_bfloat16 l1 = __float2bfloat16_rn(f1 - __bfloat162float(h1));
            __nv_bfloat16 l2 = __float2bfloat16_rn(f2 - __bfloat162float(h2));
            __nv_bfloat16 l3 = __float2bfloat16_rn(f3 - __bfloat162float(h3));
            uint32_t hw0 = (uint32_t)__bfloat16_as_ushort(h0) | ((uint32_t)__bfloat16_as_ushort(h1) << 16);
            uint32_t hw1 = (uint32_t)__bfloat16_as_ushort(h2) | ((uint32_t)__bfloat16_as_ushort(h3) << 16);
            uint32_t lw0 = (uint32_t)__bfloat16_as_ushort(l0) | ((uint32_t)__bfloat16_as_ushort(l1) << 16);
            uint32_t lw1 = (uint32_t)__bfloat16_as_ushort(l2) | ((uint32_t)__bfloat16_as_ushort(l3) << 16);
            // row = rr (128B/row); 8B granule pair inside 16B swizzle unit
            uint32_t kbyte = (uint32_t)(i4 * 8);
            uint32_t off = (uint32_t)(rr * 128) + ((kbyte & ~15u) ^ (((uint32_t)rr & 7u) << 4)) + (kbyte & 8u);
            *(uint2*)(hi_t + off) = make_uint2(hw0, hw1);
            *(uint2*)(lo_t + off) = make_uint2(lw0, lw1);
        }
        if (isx) xn[rr] = norm; else yn[rr] = norm;
    }
    __syncthreads();

    // ---- Warp tiling: 2x4 warps, warp tile 64 (m) x 32 (n) ----
    const int wy = wid >> 2;            // 0..1
    const int wx = wid & 3;             // 0..3
    const int m_warp = wy * 64;
    const int n_warp = wx * 32;

    // ldmatrix per-thread invariants
    const uint32_t xorv  = ((uint32_t)lane & 7u) << 4;
    const uint32_t rowA  = (uint32_t)(m_warp + (lane & 15));         // + mt*16
    const uint32_t gA    = (uint32_t)(lane & 16);                    // k granule 0/16
    const uint32_t rowB  = (uint32_t)(n_warp + (lane & 7) + ((lane >> 4) & 1) * 8);  // + ntp*16
    const uint32_t gB    = (uint32_t)((lane & 8) << 1);              // k granule 0/16

    const uint32_t baseA_row = rowA * 128u;
    const uint32_t baseB_row = rowB * 128u;

    float c[4][4][4];
    #pragma unroll
    for (int mt = 0; mt < 4; mt++)
        #pragma unroll
        for (int nt = 0; nt < 4; nt++)
            #pragma unroll
            for (int q = 0; q < 4; q++) c[mt][nt][q] = 0.0f;

    const uint32_t abase[3] = { sbase + SM_XHI, sbase + SM_XHI, sbase + SM_XLO };
    const uint32_t bbase[3] = { sbase + SM_YHI, sbase + SM_YLO, sbase + SM_YHI };

    #pragma unroll
    for (int p = 0; p < 3; p++) {
        const uint32_t abA = abase[p] + baseA_row;
        const uint32_t abB = bbase[p] + baseB_row;
        #pragma unroll
        for (int kk = 0; kk < 4; kk++) {
            const uint32_t kbA = ((uint32_t)(kk * 32) + gA) ^ xorv;
            const uint32_t kbB = ((uint32_t)(kk * 32) + gB) ^ xorv;

            uint32_t a[4][4];
            #pragma unroll
            for (int mt = 0; mt < 4; mt++)
                ldsm_x4(abA + (uint32_t)mt * 2048u + kbA,
                        a[mt][0], a[mt][1], a[mt][2], a[mt][3]);

            uint32_t bf[4][2];
            #pragma unroll
            for (int ntp = 0; ntp < 2; ntp++) {
                uint32_t r0, r1, r2, r3;
                ldsm_x4(abB + (uint32_t)ntp * 2048u + kbB, r0, r1, r2, r3);
                bf[ntp * 2 + 0][0] = r0; bf[ntp * 2 + 0][1] = r1;
                bf[ntp * 2 + 1][0] = r2; bf[ntp * 2 + 1][1] = r3;
            }

            #pragma unroll
            for (int mt = 0; mt < 4; mt++)
                #pragma unroll
                for (int nt = 0; nt < 4; nt++)
                    mma16816(c[mt][nt][0], c[mt][nt][1], c[mt][nt][2], c[mt][nt][3],
                             a[mt][0], a[mt][1], a[mt][2], a[mt][3],
                             bf[nt][0], bf[nt][1]);
        }
    }

    // ---- Epilogue: out = dot + xn[i] + yn[j], direct STG.64 in fragment layout ----
    const int mrow = (lane >> 2);        // 0..7
    const int ncol = 2 * (lane & 3);     // 0,2,4,6

    float2 ynr[4];
    #pragma unroll
    for (int nt = 0; nt < 4; nt++)
        ynr[nt] = *(const float2*)(yn + n_warp + nt * 8 + ncol);

    #pragma unroll
    for (int mt = 0; mt < 4; mt++) {
        const int m_lo = m_warp + mt * 16 + mrow;
        const int m_hi = m_lo + 8;
        const float xn_lo = xn[m_lo];
        const float xn_hi = xn[m_hi];
        float* row_lo = ob + (size_t)(i0 + m_lo) * n + j0 + n_warp;
        float* row_hi = ob + (size_t)(i0 + m_hi) * n + j0 + n_warp;
        #pragma unroll
        for (int nt = 0; nt < 4; nt++) {
            float2 o0, o1;
            o0.x = c[mt][nt][0] + xn_lo + ynr[nt].x;
            o0.y = c[mt][nt][1] + xn_lo + ynr[nt].y;
            o1.x = c[mt][nt][2] + xn_hi + ynr[nt].x;
            o1.y = c[mt][nt][3] + xn_hi + ynr[nt].y;
            *(float2*)(row_lo + nt * 8 + ncol) = o0;
            *(float2*)(row_hi + nt * 8 + ncol) = o1;
        }
    }
}

extern "C" void kernel_launch(void* const* d_in, const int* in_sizes, int n_in,
                              void* d_out, int out_size) {
    const float* x = (const float*)d_in[0];
    const float* y = (const float*)d_in[1];
    float* out = (float*)d_out;

    const int B = 2;
    int n = in_sizes[0] / (B * Dk);       // 2048
    if (n <= 0) n = 2048;

    cudaFuncSetAttribute(PairwiseDistance_mma_kernel,
                         cudaFuncAttributeMaxDynamicSharedMemorySize, SM_TOTAL);

    dim3 grid(n / TILE, n / TILE, B);
    PairwiseDistance_mma_kernel<<<grid, NTHREADS, SM_TOTAL>>>(x, y, out, n);
}